// round 1
// baseline (speedup 1.0000x reference)
#include <cuda_runtime.h>
#include <cuda_bf16.h>
#include <cstdint>

// Problem constants
#define BB 2
#define NN 512
#define DD 64        // NODE_DIM / EDGE_DIM
#define HH 128       // HIDDEN
#define RTOT (BB*NN) // 1024 rows

// Scratch (device globals — no allocation allowed)
__device__ float g_hib[RTOT * HH];  // hi + b_edge
__device__ float g_hj [RTOT * HH];  // hj
__device__ float g_msg[RTOT * HH];  // message

// ---------------------------------------------------------------------------
// Kernel A: hi_b[r][h] = b_edge[h] + nf[r] . W1[:,h] ; hj[r][h] = nf[r] . W2[:,h]
// grid = 1024, block = 128
// ---------------------------------------------------------------------------
__global__ void prep_kernel(const float* __restrict__ nf,
                            const float* __restrict__ W_edge,
                            const float* __restrict__ b_edge) {
    int r = blockIdx.x;
    int h = threadIdx.x;
    __shared__ float nfs[DD];
    if (h < DD) nfs[h] = nf[r * DD + h];
    __syncthreads();
    float a1 = b_edge[h];
    float a2 = 0.f;
#pragma unroll
    for (int k = 0; k < DD; k++) {
        float x = nfs[k];
        a1 = fmaf(x, W_edge[k * HH + h], a1);           // W1
        a2 = fmaf(x, W_edge[(DD + k) * HH + h], a2);    // W2
    }
    g_hib[r * HH + h] = a1;
    g_hj [r * HH + h] = a2;
}

// ---------------------------------------------------------------------------
// Kernel B: main fused edge kernel.
// One CTA per (b,i). 256 threads: h = tid&127, jg = tid>>7 (two j-halves).
// Each thread keeps W3[:,h] (64 floats) in registers for the whole CTA.
// For each j: edge_h = relu(ef[j].W3[:,h] + hib[h] + hj[j][h]); store; msg += adj[j]*edge_h.
// ---------------------------------------------------------------------------
#define W3PAD 68   // padded row stride (floats), 16B-aligned, reduces LDS conflicts
#define JT 8       // j-tile

__global__ __launch_bounds__(256, 2)
void edge_kernel(const float* __restrict__ ef,
                 const float* __restrict__ adj,
                 const float* __restrict__ W_edge,
                 float* __restrict__ edge_out) {
    __shared__ __align__(16) float w3t[HH * W3PAD]; // transposed W3: [h][k]
    __shared__ __align__(16) float efs[JT * DD];    // staged edge features
    __shared__ float ms[256];

    const int r   = blockIdx.x;        // b*N + i
    const int b   = r >> 9;
    const int tid = threadIdx.x;
    const int h   = tid & 127;
    const int jg  = tid >> 7;          // 0 or 1

    // Load W3 (rows 128..191 of W_edge) transposed into SMEM (coalesced GMEM read)
    for (int t = tid; t < DD * HH; t += 256) {
        int k  = t >> 7;      // 0..63
        int hh = t & 127;     // 0..127
        w3t[hh * W3PAD + k] = W_edge[(2 * DD + k) * HH + hh];
    }
    __syncthreads();

    // Pull this thread's W3 column into registers (once per CTA)
    float4 w3r[16];
    const float4* w3p = reinterpret_cast<const float4*>(&w3t[h * W3PAD]);
#pragma unroll
    for (int q = 0; q < 16; q++) w3r[q] = w3p[q];

    const float  hib    = g_hib[r * HH + h];
    const float* hjrow  = g_hj + (size_t)(b << 9) * HH;     // hj for this batch
    const float* efrow  = ef  + (size_t)r * (NN * DD);
    const float* adjrow = adj + (size_t)r * NN;
    float*       erow   = edge_out + (size_t)r * (NN * HH);

    float msg = 0.f;

    for (int j0 = 0; j0 < NN; j0 += JT) {
        __syncthreads();  // protect efs from previous tile's readers
        // stage JT*64 = 512 floats, 2 per thread, coalesced
#pragma unroll
        for (int t = 0; t < 2; t++) {
            int idx = tid + t * 256;
            efs[idx] = efrow[j0 * DD + idx];
        }
        __syncthreads();

#pragma unroll
        for (int jj = 0; jj < 4; jj++) {
            const int jl = jg * 4 + jj;      // local j in tile
            const int j  = j0 + jl;
            const float4* ep = reinterpret_cast<const float4*>(&efs[jl * DD]);
            float acc = 0.f;
#pragma unroll
            for (int q = 0; q < 16; q++) {
                float4 e = ep[q];
                acc = fmaf(e.x, w3r[q].x, acc);
                acc = fmaf(e.y, w3r[q].y, acc);
                acc = fmaf(e.z, w3r[q].z, acc);
                acc = fmaf(e.w, w3r[q].w, acc);
            }
            float v = acc + hib + hjrow[j * HH + h];
            v = fmaxf(v, 0.f);
            erow[(size_t)j * HH + h] = v;
            msg = fmaf(adjrow[j], v, msg);
        }
    }

    // reduce the two jg partials
    ms[tid] = msg;
    __syncthreads();
    if (jg == 0) g_msg[r * HH + h] = ms[h] + ms[128 + h];
}

// ---------------------------------------------------------------------------
// Kernel C: ending = relu(msg . W_feat[:128] + nf . W_feat[128:] + b_feat)
// grid = 1024, block = 128
// ---------------------------------------------------------------------------
__global__ void final_kernel(const float* __restrict__ nf,
                             const float* __restrict__ W_feat,
                             const float* __restrict__ b_feat,
                             float* __restrict__ out) {
    int r = blockIdx.x;
    int h = threadIdx.x;
    __shared__ float msh[HH];
    __shared__ float nfs[DD];
    msh[h] = g_msg[r * HH + h];
    if (h < DD) nfs[h] = nf[r * DD + h];
    __syncthreads();
    float acc = b_feat[h];
#pragma unroll 4
    for (int k = 0; k < HH; k++)
        acc = fmaf(msh[k], W_feat[k * HH + h], acc);
#pragma unroll 4
    for (int k = 0; k < DD; k++)
        acc = fmaf(nfs[k], W_feat[(HH + k) * HH + h], acc);
    out[r * HH + h] = fmaxf(acc, 0.f);
}

// ---------------------------------------------------------------------------
// kernel_launch
// Inputs (metadata order):
//  0 node_feature (2,512,64)   1 adjacency (2,512,512)  2 target_information (2,512,64)
//  3 edge_feature (2,512,512,64) 4 node_mask (2,512)    5 W_edge (192,128)
//  6 b_edge (128)              7 W_feat (192,128)       8 b_feat (128)
// Output: [ending (2,512,128) | edge_h (2,512,512,128) | target_information (2,512,64)]
// ---------------------------------------------------------------------------
extern "C" void kernel_launch(void* const* d_in, const int* in_sizes, int n_in,
                              void* d_out, int out_size) {
    const float* nf     = (const float*)d_in[0];
    const float* adj    = (const float*)d_in[1];
    const float* target = (const float*)d_in[2];
    const float* ef     = (const float*)d_in[3];
    const float* W_edge = (const float*)d_in[5];
    const float* b_edge = (const float*)d_in[6];
    const float* W_feat = (const float*)d_in[7];
    const float* b_feat = (const float*)d_in[8];

    float* out = (float*)d_out;
    const size_t ending_elems = (size_t)RTOT * HH;            // 131072
    const size_t edgeh_elems  = (size_t)RTOT * NN * HH;       // 67108864
    float* out_ending = out;
    float* out_edgeh  = out + ending_elems;
    float* out_target = out + ending_elems + edgeh_elems;

    prep_kernel<<<RTOT, HH>>>(nf, W_edge, b_edge);
    edge_kernel<<<RTOT, 256>>>(ef, adj, W_edge, out_edgeh);
    final_kernel<<<RTOT, HH>>>(nf, W_feat, b_feat, out_ending);
    cudaMemcpyAsync(out_target, target, (size_t)RTOT * DD * sizeof(float),
                    cudaMemcpyDeviceToDevice, 0);
}

// round 2
// speedup vs baseline: 2.0944x; 2.0944x over previous
#include <cuda_runtime.h>
#include <cuda_bf16.h>
#include <cstdint>

#define BB 2
#define NN 512
#define DD 64        // NODE_DIM / EDGE_DIM
#define HH 128       // HIDDEN
#define RTOT (BB*NN) // 1024 rows
#define JBLK 4       // j-blocks of 128 per row
#define JTILE 128

// Scratch (device globals — no allocation allowed)
__device__ float g_hib[RTOT * HH];            // hi + b_edge
__device__ float g_hj [RTOT * HH];            // hj
__device__ float g_msg_part[JBLK * RTOT * HH]; // per-jblock message partials

// ---------------------------------------------------------------------------
// Kernel A: hi_b[r][h] = b_edge[h] + nf[r].W1[:,h] ; hj[r][h] = nf[r].W2[:,h]
// ---------------------------------------------------------------------------
__global__ void prep_kernel(const float* __restrict__ nf,
                            const float* __restrict__ W_edge,
                            const float* __restrict__ b_edge) {
    int r = blockIdx.x;
    int h = threadIdx.x;
    __shared__ float nfs[DD];
    if (h < DD) nfs[h] = nf[r * DD + h];
    __syncthreads();
    float a1 = b_edge[h];
    float a2 = 0.f;
#pragma unroll
    for (int k = 0; k < DD; k++) {
        float x = nfs[k];
        a1 = fmaf(x, W_edge[k * HH + h], a1);           // W1
        a2 = fmaf(x, W_edge[(DD + k) * HH + h], a2);    // W2
    }
    g_hib[r * HH + h] = a1;
    g_hj [r * HH + h] = a2;
}

// ---------------------------------------------------------------------------
// Kernel B: tf32 tensor-core edge GEMM, fused bias+ReLU+store+message.
// Grid: 4096 CTAs (r = bx>>2, jb = bx&3). CTA tile: 128 j x 128 h.
// 8 warps: wm = wid&3 (j, 32 rows), wn = wid>>2 (h, 64 cols).
// mma.sync.m16n8k8 tf32, fp32 accumulate.
// ---------------------------------------------------------------------------
#define ASTR 68    // A smem row stride (words): banks (4g+t) conflict-free
#define BSTR 136   // B smem row stride (words): banks (8t+g) conflict-free

#define MMA_TF32(d, a, bfr)                                                     \
    asm volatile(                                                               \
        "mma.sync.aligned.m16n8k8.row.col.f32.tf32.tf32.f32 "                   \
        "{%0,%1,%2,%3},{%4,%5,%6,%7},{%8,%9},{%0,%1,%2,%3};"                    \
        : "+f"(d[0]), "+f"(d[1]), "+f"(d[2]), "+f"(d[3])                        \
        : "r"(a[0]), "r"(a[1]), "r"(a[2]), "r"(a[3]), "r"(bfr[0]), "r"(bfr[1]))

__global__ __launch_bounds__(256, 2)
void edge_mma_kernel(const float* __restrict__ ef,
                     const float* __restrict__ adj,
                     const float* __restrict__ W_edge,
                     float* __restrict__ edge_out) {
    extern __shared__ uint32_t smem_u[];
    uint32_t* As = smem_u;                          // [128][ASTR]
    uint32_t* Bs = smem_u + JTILE * ASTR;           // [64][BSTR]
    float* hibs   = (float*)(Bs + DD * BSTR);       // [128]
    float* msgbuf = hibs + HH;                      // [4][128]

    const int bx  = blockIdx.x;
    const int r   = bx >> 2;
    const int jb  = bx & 3;
    const int b   = r >> 9;
    const int tid = threadIdx.x;
    const int lane = tid & 31;
    const int wid  = tid >> 5;
    const int wm = wid & 3;          // j-warp (4)
    const int wn = wid >> 2;         // h-warp (2)
    const int g  = lane >> 2;        // groupID
    const int t  = lane & 3;         // threadID_in_group

    // Stage B = W3 (rows 128..191 of W_edge), RN-rounded to tf32
    for (int idx = tid; idx < DD * HH; idx += 256) {
        int k = idx >> 7, h = idx & 127;
        float w = W_edge[(2 * DD + k) * HH + h];
        uint32_t u; asm("cvt.rna.tf32.f32 %0, %1;" : "=r"(u) : "f"(w));
        Bs[k * BSTR + h] = u;
    }
    // Stage A = ef[r, jb*128 : jb*128+128, :], RN-rounded to tf32
    const float* efp = ef + ((size_t)r * NN + jb * JTILE) * DD;
    for (int idx = tid; idx < JTILE * DD; idx += 256) {
        int j = idx >> 6, k = idx & 63;
        float x = efp[idx];
        uint32_t u; asm("cvt.rna.tf32.f32 %0, %1;" : "=r"(u) : "f"(x));
        As[j * ASTR + k] = u;
    }
    if (tid < HH) hibs[tid] = g_hib[r * HH + tid];
    __syncthreads();

    float acc[2][8][4];
#pragma unroll
    for (int mt = 0; mt < 2; mt++)
#pragma unroll
        for (int nt = 0; nt < 8; nt++)
#pragma unroll
            for (int c = 0; c < 4; c++) acc[mt][nt][c] = 0.f;

#pragma unroll
    for (int ks = 0; ks < 8; ks++) {
        const int k0 = ks * 8;
        uint32_t a[2][4];
#pragma unroll
        for (int mt = 0; mt < 2; mt++) {
            int row = wm * 32 + mt * 16 + g;
            a[mt][0] = As[row * ASTR + k0 + t];
            a[mt][1] = As[(row + 8) * ASTR + k0 + t];
            a[mt][2] = As[row * ASTR + k0 + t + 4];
            a[mt][3] = As[(row + 8) * ASTR + k0 + t + 4];
        }
        uint32_t bfr[8][2];
#pragma unroll
        for (int nt = 0; nt < 8; nt++) {
            int h = wn * 64 + nt * 8 + g;
            bfr[nt][0] = Bs[(k0 + t) * BSTR + h];
            bfr[nt][1] = Bs[(k0 + t + 4) * BSTR + h];
        }
#pragma unroll
        for (int mt = 0; mt < 2; mt++)
#pragma unroll
            for (int nt = 0; nt < 8; nt++)
                MMA_TF32(acc[mt][nt], a[mt], bfr[nt]);
    }

    // Epilogue: + hib[h] + hj[b,j,h], ReLU, store edge_h, message partial
    const float* adjr = adj + (size_t)r * NN + jb * JTILE;             // local j
    const float* hjb  = g_hj + ((size_t)b * NN + jb * JTILE) * HH;     // local j
    float*       eout = edge_out + ((size_t)r * NN + jb * JTILE) * HH; // local j

    float psum[16];
#pragma unroll
    for (int p = 0; p < 16; p++) psum[p] = 0.f;

#pragma unroll
    for (int mt = 0; mt < 2; mt++) {
        int j0 = wm * 32 + mt * 16 + g;
        int j1 = j0 + 8;
        float adj0 = adjr[j0];
        float adj1 = adjr[j1];
#pragma unroll
        for (int nt = 0; nt < 8; nt++) {
            int h0 = wn * 64 + nt * 8 + 2 * t;
            float2 hb  = *(const float2*)&hibs[h0];
            float2 hj0 = *(const float2*)&hjb[(size_t)j0 * HH + h0];
            float2 hj1 = *(const float2*)&hjb[(size_t)j1 * HH + h0];
            float v00 = fmaxf(acc[mt][nt][0] + hb.x + hj0.x, 0.f);
            float v01 = fmaxf(acc[mt][nt][1] + hb.y + hj0.y, 0.f);
            float v10 = fmaxf(acc[mt][nt][2] + hb.x + hj1.x, 0.f);
            float v11 = fmaxf(acc[mt][nt][3] + hb.y + hj1.y, 0.f);
            *(float2*)&eout[(size_t)j0 * HH + h0] = make_float2(v00, v01);
            *(float2*)&eout[(size_t)j1 * HH + h0] = make_float2(v10, v11);
            psum[nt * 2    ] += adj0 * v00 + adj1 * v10;
            psum[nt * 2 + 1] += adj0 * v01 + adj1 * v11;
        }
    }

    // Reduce psum across the 8 groups (lanes differing in bits 2..4)
#pragma unroll
    for (int s = 4; s < 32; s <<= 1)
#pragma unroll
        for (int p = 0; p < 16; p++)
            psum[p] += __shfl_xor_sync(0xffffffffu, psum[p], s);

    if (lane < 4) {
#pragma unroll
        for (int nt = 0; nt < 8; nt++) {
            msgbuf[wm * HH + wn * 64 + nt * 8 + 2 * lane    ] = psum[nt * 2];
            msgbuf[wm * HH + wn * 64 + nt * 8 + 2 * lane + 1] = psum[nt * 2 + 1];
        }
    }
    __syncthreads();
    if (tid < HH) {
        float m = msgbuf[tid] + msgbuf[HH + tid] + msgbuf[2 * HH + tid] + msgbuf[3 * HH + tid];
        g_msg_part[((size_t)jb * RTOT + r) * HH + tid] = m;
    }
}

// ---------------------------------------------------------------------------
// Kernel C: ending = relu(msg.W_feat[:128] + nf.W_feat[128:] + b_feat)
// ---------------------------------------------------------------------------
__global__ void final_kernel(const float* __restrict__ nf,
                             const float* __restrict__ W_feat,
                             const float* __restrict__ b_feat,
                             float* __restrict__ out) {
    int r = blockIdx.x;
    int h = threadIdx.x;
    __shared__ float msh[HH];
    __shared__ float nfs[DD];
    {
        float m = g_msg_part[(size_t)r * HH + h]
                + g_msg_part[((size_t)RTOT + r) * HH + h]
                + g_msg_part[((size_t)2 * RTOT + r) * HH + h]
                + g_msg_part[((size_t)3 * RTOT + r) * HH + h];
        msh[h] = m;
    }
    if (h < DD) nfs[h] = nf[r * DD + h];
    __syncthreads();
    float acc = b_feat[h];
#pragma unroll 4
    for (int k = 0; k < HH; k++)
        acc = fmaf(msh[k], W_feat[k * HH + h], acc);
#pragma unroll 4
    for (int k = 0; k < DD; k++)
        acc = fmaf(nfs[k], W_feat[(HH + k) * HH + h], acc);
    out[r * HH + h] = fmaxf(acc, 0.f);
}

// ---------------------------------------------------------------------------
extern "C" void kernel_launch(void* const* d_in, const int* in_sizes, int n_in,
                              void* d_out, int out_size) {
    const float* nf     = (const float*)d_in[0];
    const float* adj    = (const float*)d_in[1];
    const float* target = (const float*)d_in[2];
    const float* ef     = (const float*)d_in[3];
    const float* W_edge = (const float*)d_in[5];
    const float* b_edge = (const float*)d_in[6];
    const float* W_feat = (const float*)d_in[7];
    const float* b_feat = (const float*)d_in[8];

    float* out = (float*)d_out;
    const size_t ending_elems = (size_t)RTOT * HH;
    const size_t edgeh_elems  = (size_t)RTOT * NN * HH;
    float* out_ending = out;
    float* out_edgeh  = out + ending_elems;
    float* out_target = out + ending_elems + edgeh_elems;

    const int smem_bytes = (JTILE * ASTR + DD * BSTR) * 4 + (HH + 4 * HH) * 4;
    cudaFuncSetAttribute(edge_mma_kernel,
                         cudaFuncAttributeMaxDynamicSharedMemorySize, smem_bytes);

    prep_kernel<<<RTOT, HH>>>(nf, W_edge, b_edge);
    edge_mma_kernel<<<RTOT * JBLK, 256, smem_bytes>>>(ef, adj, W_edge, out_edgeh);
    final_kernel<<<RTOT, HH>>>(nf, W_feat, b_feat, out_ending);
    cudaMemcpyAsync(out_target, target, (size_t)RTOT * DD * sizeof(float),
                    cudaMemcpyDeviceToDevice, 0);
}

// round 3
// speedup vs baseline: 2.5772x; 1.2306x over previous
#include <cuda_runtime.h>
#include <cuda_bf16.h>
#include <cstdint>

#define BB 2
#define NN 512
#define DD 64        // NODE_DIM / EDGE_DIM
#define HH 128       // HIDDEN
#define RTOT (BB*NN) // 1024 rows
#define JBLK 8       // j-blocks of 64 per row
#define JTILE 64

// Scratch (device globals — no allocation allowed)
__device__ float g_hib[RTOT * HH];             // hi + b_edge
__device__ float g_hj [RTOT * HH];             // hj
__device__ float g_msg_part[JBLK * RTOT * HH]; // per-jblock message partials

// ---------------------------------------------------------------------------
// Kernel A: hi_b[r][h] = b_edge[h] + nf[r].W1[:,h] ; hj[r][h] = nf[r].W2[:,h]
// 4 rows per 512-thread block.
// ---------------------------------------------------------------------------
__global__ __launch_bounds__(512)
void prep_kernel(const float* __restrict__ nf,
                 const float* __restrict__ W_edge,
                 const float* __restrict__ b_edge) {
    const int tid = threadIdx.x;
    const int rl  = tid >> 7;                 // row within block (0..3)
    const int h   = tid & 127;
    const int r   = blockIdx.x * 4 + rl;
    __shared__ float nfs[4][DD];
    if (h < DD) nfs[rl][h] = nf[r * DD + h];
    __syncthreads();
    float a1 = b_edge[h];
    float a2 = 0.f;
#pragma unroll
    for (int k = 0; k < DD; k++) {
        float x = nfs[rl][k];
        a1 = fmaf(x, W_edge[k * HH + h], a1);           // W1
        a2 = fmaf(x, W_edge[(DD + k) * HH + h], a2);    // W2
    }
    g_hib[r * HH + h] = a1;
    g_hj [r * HH + h] = a2;
}

// ---------------------------------------------------------------------------
// Kernel B: tf32 tensor-core edge GEMM, fused bias+ReLU+store+message.
// Grid: 8192 CTAs (r = bx>>3, jb = bx&7). CTA tile: 64 j x 128 h.
// 8 warps: wm = wid&3 (16 j rows each), wn = wid>>2 (64 h cols each).
// Warp tile 16x64 -> acc = 32 regs/thread; no spills at 128-reg cap.
// ---------------------------------------------------------------------------
#define ASTR 68    // A smem row stride (words): bank = 4g+t, conflict-free
#define BSTR 136   // B smem row stride (words): bank = 8(t+nt)+g, conflict-free

#define MMA_TF32(d, a, bfr)                                                     \
    asm volatile(                                                               \
        "mma.sync.aligned.m16n8k8.row.col.f32.tf32.tf32.f32 "                   \
        "{%0,%1,%2,%3},{%4,%5,%6,%7},{%8,%9},{%0,%1,%2,%3};"                    \
        : "+f"(d[0]), "+f"(d[1]), "+f"(d[2]), "+f"(d[3])                        \
        : "r"(a[0]), "r"(a[1]), "r"(a[2]), "r"(a[3]), "r"(bfr[0]), "r"(bfr[1]))

__global__ __launch_bounds__(256, 2)
void edge_mma_kernel(const float* __restrict__ ef,
                     const float* __restrict__ adj,
                     const float* __restrict__ W_edge,
                     float* __restrict__ edge_out) {
    extern __shared__ uint32_t smem_u[];
    uint32_t* As = smem_u;                          // [64][ASTR]
    uint32_t* Bs = smem_u + JTILE * ASTR;           // [64][BSTR]
    float* hibs   = (float*)(Bs + DD * BSTR);       // [128]
    float* msgbuf = hibs + HH;                      // [4][128]

    const int bx  = blockIdx.x;
    const int r   = bx >> 3;
    const int jb  = bx & 7;
    const int b   = r >> 9;
    const int tid = threadIdx.x;
    const int lane = tid & 31;
    const int wid  = tid >> 5;
    const int wm = wid & 3;          // j-warp (4), 16 rows each
    const int wn = wid >> 2;         // h-warp (2), 64 cols each
    const int g  = lane >> 2;        // groupID
    const int t  = lane & 3;         // threadID_in_group

    // Stage B = W3 (rows 128..191 of W_edge), RN-rounded to tf32
#pragma unroll
    for (int it = 0; it < (DD * HH) / 256; it++) {
        int idx = it * 256 + tid;
        int k = idx >> 7, h = idx & 127;
        float w = W_edge[(2 * DD + k) * HH + h];
        uint32_t u; asm("cvt.rna.tf32.f32 %0, %1;" : "=r"(u) : "f"(w));
        Bs[k * BSTR + h] = u;
    }
    // Stage A = ef[r, jb*64 : jb*64+64, :], RN-rounded to tf32
    const float* efp = ef + ((size_t)r * NN + jb * JTILE) * DD;
#pragma unroll
    for (int it = 0; it < (JTILE * DD) / 256; it++) {
        int idx = it * 256 + tid;
        int j = idx >> 6, k = idx & 63;
        float x = efp[idx];
        uint32_t u; asm("cvt.rna.tf32.f32 %0, %1;" : "=r"(u) : "f"(x));
        As[j * ASTR + k] = u;
    }
    if (tid < HH) hibs[tid] = g_hib[r * HH + tid];
    __syncthreads();

    float acc[8][4];
#pragma unroll
    for (int nt = 0; nt < 8; nt++)
#pragma unroll
        for (int c = 0; c < 4; c++) acc[nt][c] = 0.f;

#pragma unroll
    for (int ks = 0; ks < 8; ks++) {
        const int k0 = ks * 8;
        uint32_t a[4];
        {
            int row = wm * 16 + g;
            a[0] = As[row * ASTR + k0 + t];
            a[1] = As[(row + 8) * ASTR + k0 + t];
            a[2] = As[row * ASTR + k0 + t + 4];
            a[3] = As[(row + 8) * ASTR + k0 + t + 4];
        }
#pragma unroll
        for (int nt = 0; nt < 8; nt++) {
            uint32_t bfr[2];
            int h = wn * 64 + nt * 8 + g;
            bfr[0] = Bs[(k0 + t) * BSTR + h];
            bfr[1] = Bs[(k0 + t + 4) * BSTR + h];
            MMA_TF32(acc[nt], a, bfr);
        }
    }

    // Epilogue: + hib[h] + hj[b,j,h], ReLU, store edge_h, message partial
    const float* adjr = adj + (size_t)r * NN + jb * JTILE;
    const float* hjb  = g_hj + ((size_t)b * NN + jb * JTILE) * HH;
    float*       eout = edge_out + ((size_t)r * NN + jb * JTILE) * HH;

    float psum[16];
#pragma unroll
    for (int p = 0; p < 16; p++) psum[p] = 0.f;

    {
        const int j0 = wm * 16 + g;
        const int j1 = j0 + 8;
        const float adj0 = adjr[j0];
        const float adj1 = adjr[j1];
#pragma unroll
        for (int nt = 0; nt < 8; nt++) {
            int h0 = wn * 64 + nt * 8 + 2 * t;
            float2 hb  = *(const float2*)&hibs[h0];
            float2 hj0 = *(const float2*)&hjb[(size_t)j0 * HH + h0];
            float2 hj1 = *(const float2*)&hjb[(size_t)j1 * HH + h0];
            float v00 = fmaxf(acc[nt][0] + hb.x + hj0.x, 0.f);
            float v01 = fmaxf(acc[nt][1] + hb.y + hj0.y, 0.f);
            float v10 = fmaxf(acc[nt][2] + hb.x + hj1.x, 0.f);
            float v11 = fmaxf(acc[nt][3] + hb.y + hj1.y, 0.f);
            *(float2*)&eout[(size_t)j0 * HH + h0] = make_float2(v00, v01);
            *(float2*)&eout[(size_t)j1 * HH + h0] = make_float2(v10, v11);
            psum[nt * 2    ] += adj0 * v00 + adj1 * v10;
            psum[nt * 2 + 1] += adj0 * v01 + adj1 * v11;
        }
    }

    // Reduce psum across the 8 groups (bits 2..4 of lane)
#pragma unroll
    for (int s = 4; s < 32; s <<= 1)
#pragma unroll
        for (int p = 0; p < 16; p++)
            psum[p] += __shfl_xor_sync(0xffffffffu, psum[p], s);

    if (lane < 4) {
#pragma unroll
        for (int nt = 0; nt < 8; nt++) {
            msgbuf[wm * HH + wn * 64 + nt * 8 + 2 * lane    ] = psum[nt * 2];
            msgbuf[wm * HH + wn * 64 + nt * 8 + 2 * lane + 1] = psum[nt * 2 + 1];
        }
    }
    __syncthreads();
    if (tid < HH) {
        float m = msgbuf[tid] + msgbuf[HH + tid] + msgbuf[2 * HH + tid] + msgbuf[3 * HH + tid];
        g_msg_part[((size_t)jb * RTOT + r) * HH + tid] = m;
    }
}

// ---------------------------------------------------------------------------
// Kernel C: ending = relu(msg.W_feat[:128] + nf.W_feat[128:] + b_feat)
// 4 rows per 512-thread block.
// ---------------------------------------------------------------------------
__global__ __launch_bounds__(512)
void final_kernel(const float* __restrict__ nf,
                  const float* __restrict__ W_feat,
                  const float* __restrict__ b_feat,
                  float* __restrict__ out) {
    const int tid = threadIdx.x;
    const int rl  = tid >> 7;
    const int h   = tid & 127;
    const int r   = blockIdx.x * 4 + rl;
    __shared__ float msh[4][HH];
    __shared__ float nfs[4][DD];
    {
        float m = 0.f;
#pragma unroll
        for (int p = 0; p < JBLK; p++)
            m += g_msg_part[((size_t)p * RTOT + r) * HH + h];
        msh[rl][h] = m;
    }
    if (h < DD) nfs[rl][h] = nf[r * DD + h];
    __syncthreads();
    float acc = b_feat[h];
#pragma unroll 4
    for (int k = 0; k < HH; k++)
        acc = fmaf(msh[rl][k], W_feat[k * HH + h], acc);
#pragma unroll 4
    for (int k = 0; k < DD; k++)
        acc = fmaf(nfs[rl][k], W_feat[(HH + k) * HH + h], acc);
    out[r * HH + h] = fmaxf(acc, 0.f);
}

// ---------------------------------------------------------------------------
extern "C" void kernel_launch(void* const* d_in, const int* in_sizes, int n_in,
                              void* d_out, int out_size) {
    const float* nf     = (const float*)d_in[0];
    const float* adj    = (const float*)d_in[1];
    const float* target = (const float*)d_in[2];
    const float* ef     = (const float*)d_in[3];
    const float* W_edge = (const float*)d_in[5];
    const float* b_edge = (const float*)d_in[6];
    const float* W_feat = (const float*)d_in[7];
    const float* b_feat = (const float*)d_in[8];

    float* out = (float*)d_out;
    const size_t ending_elems = (size_t)RTOT * HH;
    const size_t edgeh_elems  = (size_t)RTOT * NN * HH;
    float* out_ending = out;
    float* out_edgeh  = out + ending_elems;
    float* out_target = out + ending_elems + edgeh_elems;

    const int smem_bytes = (JTILE * ASTR + DD * BSTR) * 4 + (HH + 4 * HH) * 4;
    cudaFuncSetAttribute(edge_mma_kernel,
                         cudaFuncAttributeMaxDynamicSharedMemorySize, smem_bytes);

    cudaMemcpyAsync(out_target, target, (size_t)RTOT * DD * sizeof(float),
                    cudaMemcpyDeviceToDevice, 0);
    prep_kernel<<<RTOT / 4, 512>>>(nf, W_edge, b_edge);
    edge_mma_kernel<<<RTOT * JBLK, 256, smem_bytes>>>(ef, adj, W_edge, out_edgeh);
    final_kernel<<<RTOT / 4, 512>>>(nf, W_feat, b_feat, out_ending);
}

// round 4
// speedup vs baseline: 2.8359x; 1.1004x over previous
#include <cuda_runtime.h>
#include <cuda_bf16.h>
#include <cstdint>

#define BB 2
#define NN 512
#define DD 64        // NODE_DIM / EDGE_DIM
#define HH 128       // HIDDEN
#define RTOT (BB*NN) // 1024 rows
#define JBLK 8       // j-blocks of 64 per row
#define JTILE 64
#define NTILES (RTOT*JBLK) // 8192

#define ASTR 68      // A smem row stride (words)
#define BSTR 136     // B smem row stride (words), staging only

// SMEM word offsets
#define AS_WORDS (JTILE*ASTR)        // 4352 per buffer
#define BS_OFF   (2*AS_WORDS)        // 8704
#define HIB_OFF  (BS_OFF + DD*BSTR)  // 17408
#define MSG_OFF  (HIB_OFF + 2*HH)    // 17664
#define SMEM_WORDS (MSG_OFF + 2*HH)  // 17920 -> 71680 bytes

// Scratch (device globals — no allocation allowed)
__device__ float g_hib[RTOT * HH];             // hi + b_edge
__device__ float g_hj [RTOT * HH];             // hj
__device__ float g_msg_part[JBLK * RTOT * HH]; // per-jblock message partials

// ---------------------------------------------------------------------------
// Kernel A: hi_b[r][h] = b_edge[h] + nf[r].W1[:,h] ; hj[r][h] = nf[r].W2[:,h]
// ---------------------------------------------------------------------------
__global__ __launch_bounds__(512)
void prep_kernel(const float* __restrict__ nf,
                 const float* __restrict__ W_edge,
                 const float* __restrict__ b_edge) {
    const int tid = threadIdx.x;
    const int rl  = tid >> 7;
    const int h   = tid & 127;
    const int r   = blockIdx.x * 4 + rl;
    __shared__ float nfs[4][DD];
    if (h < DD) nfs[rl][h] = nf[r * DD + h];
    __syncthreads();
    float a1 = b_edge[h];
    float a2 = 0.f;
#pragma unroll
    for (int k = 0; k < DD; k++) {
        float x = nfs[rl][k];
        a1 = fmaf(x, W_edge[k * HH + h], a1);
        a2 = fmaf(x, W_edge[(DD + k) * HH + h], a2);
    }
    g_hib[r * HH + h] = a1;
    g_hj [r * HH + h] = a2;
}

// ---------------------------------------------------------------------------
// Kernel B: PERSISTENT tf32 edge GEMM. Grid = #SMs, 256 thr.
// W3 fragments live in registers for the whole kernel (loaded once).
// A tiles double-buffered via cp.async. CTA tile 64j x 128h.
// 8 warps: wm = wid&1 (32 j rows), wn = wid>>1 (32 h cols). Warp tile 32x32.
// ---------------------------------------------------------------------------
#define MMA_TF32(d, a, bfr)                                                     \
    asm volatile(                                                               \
        "mma.sync.aligned.m16n8k8.row.col.f32.tf32.tf32.f32 "                   \
        "{%0,%1,%2,%3},{%4,%5,%6,%7},{%8,%9},{%0,%1,%2,%3};"                    \
        : "+f"(d[0]), "+f"(d[1]), "+f"(d[2]), "+f"(d[3])                        \
        : "r"(a[0]), "r"(a[1]), "r"(a[2]), "r"(a[3]), "r"(bfr[0]), "r"(bfr[1]))

__device__ __forceinline__ void prefetch_tile(const float* __restrict__ ef,
                                              int tile, int buf,
                                              uint32_t smem_base, int tid) {
    const int r  = tile >> 3;
    const int jb = tile & 7;
    const float4* src = (const float4*)(ef + ((size_t)r * NN + jb * JTILE) * DD);
#pragma unroll
    for (int it = 0; it < 4; it++) {
        int c = tid + it * 256;
        int j = c >> 4, q = c & 15;
        uint32_t dst = smem_base + (uint32_t)(buf * AS_WORDS + j * ASTR + q * 4) * 4u;
        asm volatile("cp.async.cg.shared.global [%0], [%1], 16;" :: "r"(dst), "l"(src + c));
    }
    if (tid < 32) {
        uint32_t dst = smem_base + (uint32_t)(HIB_OFF + buf * HH + tid * 4) * 4u;
        const float4* hsrc = (const float4*)(g_hib + (size_t)r * HH) + tid;
        asm volatile("cp.async.cg.shared.global [%0], [%1], 16;" :: "r"(dst), "l"(hsrc));
    }
}

__global__ __launch_bounds__(256, 1)
void edge_mma_persistent(const float* __restrict__ ef,
                         const float* __restrict__ adj,
                         const float* __restrict__ W_edge,
                         float* __restrict__ edge_out) {
    extern __shared__ float smem_f[];
    float* As     = smem_f;                 // [2][64][ASTR], raw fp32
    float* Bs     = smem_f + BS_OFF;        // [64][BSTR], staging only
    float* hibs2  = smem_f + HIB_OFF;       // [2][128]
    float* msgbuf = smem_f + MSG_OFF;       // [2][128]
    const uint32_t smem_base = (uint32_t)__cvta_generic_to_shared(smem_f);

    const int tid  = threadIdx.x;
    const int lane = tid & 31;
    const int wid  = tid >> 5;
    const int wm = wid & 1;          // 2 j-groups of 32 rows
    const int wn = wid >> 1;         // 4 h-groups of 32 cols
    const int g  = lane >> 2;
    const int t  = lane & 3;
    const int gstride = gridDim.x;

    // ---- One-time: stage W3 and pull fragments into registers ----
#pragma unroll
    for (int it = 0; it < (DD * HH) / 256; it++) {
        int idx = it * 256 + tid;
        int k = idx >> 7, h = idx & 127;
        Bs[k * BSTR + h] = W_edge[(2 * DD + k) * HH + h];
    }
    __syncthreads();

    uint32_t bfr[8][4][2];
#pragma unroll
    for (int ks = 0; ks < 8; ks++) {
#pragma unroll
        for (int nt = 0; nt < 4; nt++) {
            int h = wn * 32 + nt * 8 + g;
            float b0 = Bs[(ks * 8 + t) * BSTR + h];
            float b1 = Bs[(ks * 8 + t + 4) * BSTR + h];
            asm("cvt.rna.tf32.f32 %0, %1;" : "=r"(bfr[ks][nt][0]) : "f"(b0));
            asm("cvt.rna.tf32.f32 %0, %1;" : "=r"(bfr[ks][nt][1]) : "f"(b1));
        }
    }

    // ---- Prologue prefetch ----
    if (blockIdx.x < NTILES)
        prefetch_tile(ef, blockIdx.x, 0, smem_base, tid);
    asm volatile("cp.async.commit_group;" ::: "memory");

    int buf = 0;
    for (int tile = blockIdx.x; tile < NTILES; tile += gstride, buf ^= 1) {
        asm volatile("cp.async.wait_group 0;" ::: "memory");
        __syncthreads();

        const int nexttile = tile + gstride;
        if (nexttile < NTILES)
            prefetch_tile(ef, nexttile, buf ^ 1, smem_base, tid);
        asm volatile("cp.async.commit_group;" ::: "memory");

        const float* Ab   = As + buf * AS_WORDS;
        const float* hibs = hibs2 + buf * HH;

        float acc[2][4][4];
#pragma unroll
        for (int mt = 0; mt < 2; mt++)
#pragma unroll
            for (int nt = 0; nt < 4; nt++)
#pragma unroll
                for (int c = 0; c < 4; c++) acc[mt][nt][c] = 0.f;

#pragma unroll
        for (int ks = 0; ks < 8; ks++) {
            const int k0 = ks * 8;
            uint32_t a[2][4];
#pragma unroll
            for (int mt = 0; mt < 2; mt++) {
                int row = wm * 32 + mt * 16 + g;
                float r0 = Ab[row * ASTR + k0 + t];
                float r1 = Ab[(row + 8) * ASTR + k0 + t];
                float r2 = Ab[row * ASTR + k0 + t + 4];
                float r3 = Ab[(row + 8) * ASTR + k0 + t + 4];
                asm("cvt.rna.tf32.f32 %0, %1;" : "=r"(a[mt][0]) : "f"(r0));
                asm("cvt.rna.tf32.f32 %0, %1;" : "=r"(a[mt][1]) : "f"(r1));
                asm("cvt.rna.tf32.f32 %0, %1;" : "=r"(a[mt][2]) : "f"(r2));
                asm("cvt.rna.tf32.f32 %0, %1;" : "=r"(a[mt][3]) : "f"(r3));
            }
#pragma unroll
            for (int mt = 0; mt < 2; mt++)
#pragma unroll
                for (int nt = 0; nt < 4; nt++)
                    MMA_TF32(acc[mt][nt], a[mt], bfr[ks][nt]);
        }

        // ---- Epilogue ----
        const int r  = tile >> 3;
        const int jb = tile & 7;
        const int b  = r >> 9;
        const float* adjr = adj + (size_t)r * NN + jb * JTILE;
        const float* hjb  = g_hj + ((size_t)b * NN + jb * JTILE) * HH;
        float*       eout = edge_out + ((size_t)r * NN + jb * JTILE) * HH;

        float psum[4][2];
#pragma unroll
        for (int nt = 0; nt < 4; nt++) { psum[nt][0] = 0.f; psum[nt][1] = 0.f; }

#pragma unroll
        for (int mt = 0; mt < 2; mt++) {
            const int j0 = wm * 32 + mt * 16 + g;
            const int j1 = j0 + 8;
            const float adj0 = adjr[j0];
            const float adj1 = adjr[j1];
#pragma unroll
            for (int nt = 0; nt < 4; nt++) {
                int h0 = wn * 32 + nt * 8 + 2 * t;
                float2 hb  = *(const float2*)&hibs[h0];
                float2 hj0 = *(const float2*)&hjb[(size_t)j0 * HH + h0];
                float2 hj1 = *(const float2*)&hjb[(size_t)j1 * HH + h0];
                float v00 = fmaxf(acc[mt][nt][0] + hb.x + hj0.x, 0.f);
                float v01 = fmaxf(acc[mt][nt][1] + hb.y + hj0.y, 0.f);
                float v10 = fmaxf(acc[mt][nt][2] + hb.x + hj1.x, 0.f);
                float v11 = fmaxf(acc[mt][nt][3] + hb.y + hj1.y, 0.f);
                *(float2*)&eout[(size_t)j0 * HH + h0] = make_float2(v00, v01);
                *(float2*)&eout[(size_t)j1 * HH + h0] = make_float2(v10, v11);
                psum[nt][0] += adj0 * v00 + adj1 * v10;
                psum[nt][1] += adj0 * v01 + adj1 * v11;
            }
        }

#pragma unroll
        for (int s = 4; s < 32; s <<= 1)
#pragma unroll
            for (int nt = 0; nt < 4; nt++) {
                psum[nt][0] += __shfl_xor_sync(0xffffffffu, psum[nt][0], s);
                psum[nt][1] += __shfl_xor_sync(0xffffffffu, psum[nt][1], s);
            }

        if (lane < 4) {
#pragma unroll
            for (int nt = 0; nt < 4; nt++) {
                msgbuf[wm * HH + wn * 32 + nt * 8 + 2 * lane    ] = psum[nt][0];
                msgbuf[wm * HH + wn * 32 + nt * 8 + 2 * lane + 1] = psum[nt][1];
            }
        }
        __syncthreads();
        if (tid < HH) {
            float m = msgbuf[tid] + msgbuf[HH + tid];
            g_msg_part[((size_t)jb * RTOT + r) * HH + tid] = m;
        }
    }
}

// ---------------------------------------------------------------------------
// Kernel C: ending = relu(msg.W_feat[:128] + nf.W_feat[128:] + b_feat)
// ---------------------------------------------------------------------------
__global__ __launch_bounds__(512)
void final_kernel(const float* __restrict__ nf,
                  const float* __restrict__ W_feat,
                  const float* __restrict__ b_feat,
                  float* __restrict__ out) {
    const int tid = threadIdx.x;
    const int rl  = tid >> 7;
    const int h   = tid & 127;
    const int r   = blockIdx.x * 4 + rl;
    __shared__ float msh[4][HH];
    __shared__ float nfs[4][DD];
    {
        float m = 0.f;
#pragma unroll
        for (int p = 0; p < JBLK; p++)
            m += g_msg_part[((size_t)p * RTOT + r) * HH + h];
        msh[rl][h] = m;
    }
    if (h < DD) nfs[rl][h] = nf[r * DD + h];
    __syncthreads();
    float acc = b_feat[h];
#pragma unroll 4
    for (int k = 0; k < HH; k++)
        acc = fmaf(msh[rl][k], W_feat[k * HH + h], acc);
#pragma unroll 4
    for (int k = 0; k < DD; k++)
        acc = fmaf(nfs[rl][k], W_feat[(HH + k) * HH + h], acc);
    out[r * HH + h] = fmaxf(acc, 0.f);
}

// ---------------------------------------------------------------------------
extern "C" void kernel_launch(void* const* d_in, const int* in_sizes, int n_in,
                              void* d_out, int out_size) {
    const float* nf     = (const float*)d_in[0];
    const float* adj    = (const float*)d_in[1];
    const float* target = (const float*)d_in[2];
    const float* ef     = (const float*)d_in[3];
    const float* W_edge = (const float*)d_in[5];
    const float* b_edge = (const float*)d_in[6];
    const float* W_feat = (const float*)d_in[7];
    const float* b_feat = (const float*)d_in[8];

    float* out = (float*)d_out;
    const size_t ending_elems = (size_t)RTOT * HH;
    const size_t edgeh_elems  = (size_t)RTOT * NN * HH;
    float* out_ending = out;
    float* out_edgeh  = out + ending_elems;
    float* out_target = out + ending_elems + edgeh_elems;

    int nsm = 0;
    cudaDeviceGetAttribute(&nsm, cudaDevAttrMultiProcessorCount, 0);
    if (nsm <= 0) nsm = 148;

    const int smem_bytes = SMEM_WORDS * 4;
    cudaFuncSetAttribute(edge_mma_persistent,
                         cudaFuncAttributeMaxDynamicSharedMemorySize, smem_bytes);

    prep_kernel<<<RTOT / 4, 512>>>(nf, W_edge, b_edge);
    edge_mma_persistent<<<nsm, 256, smem_bytes>>>(ef, adj, W_edge, out_edgeh);
    cudaMemcpyAsync(out_target, target, (size_t)RTOT * DD * sizeof(float),
                    cudaMemcpyDeviceToDevice, 0);
    final_kernel<<<RTOT / 4, 512>>>(nf, W_feat, b_feat, out_ending);
}

// round 6
// speedup vs baseline: 3.3128x; 1.1682x over previous
#include <cuda_runtime.h>
#include <cuda_bf16.h>
#include <cstdint>

#define BB 2
#define NN 512
#define DD 64        // NODE_DIM / EDGE_DIM
#define HH 128       // HIDDEN
#define RTOT (BB*NN) // 1024 rows
#define JBLK 8       // j-blocks of 64 per row
#define JTILE 64
#define NTILES (RTOT*JBLK) // 8192

#define ASTR 68      // A smem row stride (words)
#define BSTR 130     // B one-time staging stride (overlaid on vbuf)
#define PAD  132     // hj / vbuf row stride (floats), 16B-aligned rows

// ---- SMEM float-index layout ----
#define A_F     0                    // 2 x 64 x ASTR = 8704
#define AS_WORDS (JTILE*ASTR)        // 4352
#define HJ_F    8704                 // 64 x PAD = 8448
#define VB_F    17152                // 64 x PAD = 8448 (also B staging, one-time)
#define B_F     VB_F
#define HIB_F   25600                // 2 x 128
#define ADJ_F   25856                // 2 x 64
#define MSGW_F  25984                // 8 x 128
#define SMEM_F  27008
#define SMEM_BYTES (SMEM_F*4)

// Scratch (device globals — no allocation allowed)
__device__ float g_hib[RTOT * HH];
__device__ float g_hj [RTOT * HH];
__device__ float g_msg_part[JBLK * RTOT * HH];

#define MMA_TF32(d, a, bfr)                                                     \
    asm volatile(                                                               \
        "mma.sync.aligned.m16n8k8.row.col.f32.tf32.tf32.f32 "                   \
        "{%0,%1,%2,%3},{%4,%5,%6,%7},{%8,%9},{%0,%1,%2,%3};"                    \
        : "+f"(d[0]), "+f"(d[1]), "+f"(d[2]), "+f"(d[3])                        \
        : "r"(a[0]), "r"(a[1]), "r"(a[2]), "r"(a[3]), "r"(bfr[0]), "r"(bfr[1]))

// ---------------------------------------------------------------------------
// Kernel A: hi_b, hj
// ---------------------------------------------------------------------------
__global__ __launch_bounds__(512)
void prep_kernel(const float* __restrict__ nf,
                 const float* __restrict__ W_edge,
                 const float* __restrict__ b_edge) {
    const int tid = threadIdx.x;
    const int rl  = tid >> 7;
    const int h   = tid & 127;
    const int r   = blockIdx.x * 4 + rl;
    __shared__ float nfs[4][DD];
    if (h < DD) nfs[rl][h] = nf[r * DD + h];
    __syncthreads();
    float a1 = b_edge[h];
    float a2 = 0.f;
#pragma unroll
    for (int k = 0; k < DD; k++) {
        float x = nfs[rl][k];
        a1 = fmaf(x, W_edge[k * HH + h], a1);
        a2 = fmaf(x, W_edge[(DD + k) * HH + h], a2);
    }
    g_hib[r * HH + h] = a1;
    g_hj [r * HH + h] = a2;
}

// ---------------------------------------------------------------------------
// Kernel B: persistent tf32 edge GEMM (legacy mma.sync), W3 in registers,
// cp.async double-buffered A/hib/adj, hj cached in SMEM per (b,jb),
// SMEM round-trip epilogue for coalesced 512B-row stores + fused message.
// Tile order jb-major: tile t -> jb = t>>10, r = t&1023.
// ---------------------------------------------------------------------------
__device__ __forceinline__ void prefetch_tile(const float* __restrict__ ef,
                                              const float* __restrict__ adj,
                                              int tile, int buf,
                                              uint32_t smem_base, int tid) {
    const int r  = tile & 1023;
    const int jb = tile >> 10;
    const float4* src = (const float4*)(ef + ((size_t)r * NN + jb * JTILE) * DD);
#pragma unroll
    for (int it = 0; it < 4; it++) {
        int c = tid + it * 256;
        int j = c >> 4, q = c & 15;
        uint32_t dst = smem_base + (uint32_t)(A_F + buf * AS_WORDS + j * ASTR + q * 4) * 4u;
        asm volatile("cp.async.cg.shared.global [%0], [%1], 16;" :: "r"(dst), "l"(src + c));
    }
    if (tid < 32) {
        uint32_t dst = smem_base + (uint32_t)(HIB_F + buf * HH + tid * 4) * 4u;
        const float4* hs = (const float4*)(g_hib + (size_t)r * HH) + tid;
        asm volatile("cp.async.cg.shared.global [%0], [%1], 16;" :: "r"(dst), "l"(hs));
    } else if (tid < 48) {
        int l = tid - 32;
        uint32_t dst = smem_base + (uint32_t)(ADJ_F + buf * JTILE + l * 4) * 4u;
        const float4* as = (const float4*)(adj + (size_t)r * NN + jb * JTILE) + l;
        asm volatile("cp.async.cg.shared.global [%0], [%1], 16;" :: "r"(dst), "l"(as));
    }
}

__global__ __launch_bounds__(256, 1)
void edge_mma_persistent(const float* __restrict__ ef,
                         const float* __restrict__ adj,
                         const float* __restrict__ W_edge,
                         float* __restrict__ edge_out) {
    extern __shared__ float smem_f[];
    const uint32_t smem_base = (uint32_t)__cvta_generic_to_shared(smem_f);

    float* As   = smem_f + A_F;
    float* hjs  = smem_f + HJ_F;
    float* vbuf = smem_f + VB_F;
    float* Bs   = smem_f + B_F;      // one-time overlay
    float* hibs = smem_f + HIB_F;
    float* adjs = smem_f + ADJ_F;
    float* msgw = smem_f + MSGW_F;

    const int tid  = threadIdx.x;
    const int lane = tid & 31;
    const int wid  = tid >> 5;
    const int wm = wid & 1;          // 2 j-groups of 32 rows
    const int wn = wid >> 1;         // 4 h-groups of 32 cols
    const int g  = lane >> 2;
    const int t  = lane & 3;

    // ---- One-time: stage W3 and pull fragments into registers ----
    for (int idx = tid; idx < DD * HH; idx += 256) {
        int k = idx >> 7, h = idx & 127;
        Bs[k * BSTR + h] = W_edge[(2 * DD + k) * HH + h];
    }
    __syncthreads();

    uint32_t bfr[8][4][2];
#pragma unroll
    for (int ks = 0; ks < 8; ks++)
#pragma unroll
        for (int nt = 0; nt < 4; nt++) {
            int h = wn * 32 + nt * 8 + g;
            float b0 = Bs[(ks * 8 + t) * BSTR + h];
            float b1 = Bs[(ks * 8 + t + 4) * BSTR + h];
            asm("cvt.rna.tf32.f32 %0, %1;" : "=r"(bfr[ks][nt][0]) : "f"(b0));
            asm("cvt.rna.tf32.f32 %0, %1;" : "=r"(bfr[ks][nt][1]) : "f"(b1));
        }
    __syncthreads();   // B region free for vbuf use

    if ((int)blockIdx.x < NTILES)
        prefetch_tile(ef, adj, blockIdx.x, 0, smem_base, tid);
    asm volatile("cp.async.commit_group;" ::: "memory");

    int buf = 0;
    int hjkey = -1;
    for (int tile = blockIdx.x; tile < NTILES; tile += gridDim.x, buf ^= 1) {
        asm volatile("cp.async.wait_group 0;" ::: "memory");
        __syncthreads();

        const int tn = tile + gridDim.x;
        if (tn < NTILES)
            prefetch_tile(ef, adj, tn, buf ^ 1, smem_base, tid);
        asm volatile("cp.async.commit_group;" ::: "memory");

        const int r  = tile & 1023;
        const int jb = tile >> 10;
        const int b  = r >> 9;

        // ---- hj tile cache: reload only when (b, jb) changes (rare) ----
        const int key = (b << 3) | jb;
        if (key != hjkey) {
            const float* hsrc = g_hj + ((size_t)b * NN + jb * JTILE) * HH;
#pragma unroll
            for (int it = 0; it < 8; it++) {
                int c = tid + it * 256;
                int j = c >> 5, l = c & 31;
                float4 v = *((const float4*)hsrc + c);
                *(float4*)&hjs[j * PAD + l * 4] = v;
            }
            hjkey = key;
            __syncthreads();
        }

        // ---- MMA loop (identical math to R4) ----
        const float* Ab = As + buf * AS_WORDS;
        float acc[2][4][4];
#pragma unroll
        for (int mt = 0; mt < 2; mt++)
#pragma unroll
            for (int nt = 0; nt < 4; nt++)
#pragma unroll
                for (int c = 0; c < 4; c++) acc[mt][nt][c] = 0.f;

#pragma unroll
        for (int ks = 0; ks < 8; ks++) {
            const int k0 = ks * 8;
            uint32_t a[2][4];
#pragma unroll
            for (int mt = 0; mt < 2; mt++) {
                int row = wm * 32 + mt * 16 + g;
                float r0 = Ab[row * ASTR + k0 + t];
                float r1 = Ab[(row + 8) * ASTR + k0 + t];
                float r2 = Ab[row * ASTR + k0 + t + 4];
                float r3 = Ab[(row + 8) * ASTR + k0 + t + 4];
                asm("cvt.rna.tf32.f32 %0, %1;" : "=r"(a[mt][0]) : "f"(r0));
                asm("cvt.rna.tf32.f32 %0, %1;" : "=r"(a[mt][1]) : "f"(r1));
                asm("cvt.rna.tf32.f32 %0, %1;" : "=r"(a[mt][2]) : "f"(r2));
                asm("cvt.rna.tf32.f32 %0, %1;" : "=r"(a[mt][3]) : "f"(r3));
            }
#pragma unroll
            for (int mt = 0; mt < 2; mt++)
#pragma unroll
                for (int nt = 0; nt < 4; nt++)
                    MMA_TF32(acc[mt][nt], a[mt], bfr[ks][nt]);
        }

        // ---- Epilogue stage 1: bias + ReLU -> vbuf (SMEM) ----
        const float* hibc = hibs + buf * HH;
#pragma unroll
        for (int mt = 0; mt < 2; mt++) {
            const int j0 = wm * 32 + mt * 16 + g;
            const int j1 = j0 + 8;
#pragma unroll
            for (int nt = 0; nt < 4; nt++) {
                int h0 = wn * 32 + nt * 8 + 2 * t;
                float2 hb  = *(const float2*)&hibc[h0];
                float2 hj0 = *(const float2*)&hjs[j0 * PAD + h0];
                float2 hj1 = *(const float2*)&hjs[j1 * PAD + h0];
                float v00 = fmaxf(acc[mt][nt][0] + hb.x + hj0.x, 0.f);
                float v01 = fmaxf(acc[mt][nt][1] + hb.y + hj0.y, 0.f);
                float v10 = fmaxf(acc[mt][nt][2] + hb.x + hj1.x, 0.f);
                float v11 = fmaxf(acc[mt][nt][3] + hb.y + hj1.y, 0.f);
                *(float2*)&vbuf[j0 * PAD + h0] = make_float2(v00, v01);
                *(float2*)&vbuf[j1 * PAD + h0] = make_float2(v10, v11);
            }
        }
        __syncthreads();

        // ---- Epilogue stage 2: coalesced store + fused message ----
        float* eout = edge_out + ((size_t)r * NN + jb * JTILE) * HH;
        float4 psum = make_float4(0.f, 0.f, 0.f, 0.f);
#pragma unroll
        for (int it = 0; it < 8; it++) {
            int j = it * 8 + wid;                  // warp-uniform row
            float4 v = *(const float4*)&vbuf[j * PAD + lane * 4];
            float a = adjs[buf * JTILE + j];
            *((float4*)(eout + (size_t)j * HH) + lane) = v;
            psum.x = fmaf(a, v.x, psum.x);
            psum.y = fmaf(a, v.y, psum.y);
            psum.z = fmaf(a, v.z, psum.z);
            psum.w = fmaf(a, v.w, psum.w);
        }
        *(float4*)&msgw[wid * HH + lane * 4] = psum;
        __syncthreads();

        if (tid < HH) {
            float m = 0.f;
#pragma unroll
            for (int w = 0; w < 8; w++) m += msgw[w * HH + tid];
            g_msg_part[((size_t)jb * RTOT + r) * HH + tid] = m;
        }
    }
}

// ---------------------------------------------------------------------------
// Kernel C: ending = relu(msg.W_feat[:128] + nf.W_feat[128:] + b_feat)
// ---------------------------------------------------------------------------
__global__ __launch_bounds__(512)
void final_kernel(const float* __restrict__ nf,
                  const float* __restrict__ W_feat,
                  const float* __restrict__ b_feat,
                  float* __restrict__ out) {
    const int tid = threadIdx.x;
    const int rl  = tid >> 7;
    const int h   = tid & 127;
    const int r   = blockIdx.x * 4 + rl;
    __shared__ float msh[4][HH];
    __shared__ float nfs[4][DD];
    {
        float m = 0.f;
#pragma unroll
        for (int p = 0; p < JBLK; p++)
            m += g_msg_part[((size_t)p * RTOT + r) * HH + h];
        msh[rl][h] = m;
    }
    if (h < DD) nfs[rl][h] = nf[r * DD + h];
    __syncthreads();
    float acc = b_feat[h];
#pragma unroll 4
    for (int k = 0; k < HH; k++)
        acc = fmaf(msh[rl][k], W_feat[k * HH + h], acc);
#pragma unroll 4
    for (int k = 0; k < DD; k++)
        acc = fmaf(nfs[rl][k], W_feat[(HH + k) * HH + h], acc);
    out[r * HH + h] = fmaxf(acc, 0.f);
}

// ---------------------------------------------------------------------------
extern "C" void kernel_launch(void* const* d_in, const int* in_sizes, int n_in,
                              void* d_out, int out_size) {
    const float* nf     = (const float*)d_in[0];
    const float* adj    = (const float*)d_in[1];
    const float* target = (const float*)d_in[2];
    const float* ef     = (const float*)d_in[3];
    const float* W_edge = (const float*)d_in[5];
    const float* b_edge = (const float*)d_in[6];
    const float* W_feat = (const float*)d_in[7];
    const float* b_feat = (const float*)d_in[8];

    float* out = (float*)d_out;
    const size_t ending_elems = (size_t)RTOT * HH;
    const size_t edgeh_elems  = (size_t)RTOT * NN * HH;
    float* out_ending = out;
    float* out_edgeh  = out + ending_elems;
    float* out_target = out + ending_elems + edgeh_elems;

    int nsm = 0;
    cudaDeviceGetAttribute(&nsm, cudaDevAttrMultiProcessorCount, 0);
    if (nsm <= 0) nsm = 148;

    cudaFuncSetAttribute(edge_mma_persistent,
                         cudaFuncAttributeMaxDynamicSharedMemorySize, SMEM_BYTES);

    prep_kernel<<<RTOT / 4, 512>>>(nf, W_edge, b_edge);
    edge_mma_persistent<<<nsm, 256, SMEM_BYTES>>>(ef, adj, W_edge, out_edgeh);
    cudaMemcpyAsync(out_target, target, (size_t)RTOT * DD * sizeof(float),
                    cudaMemcpyDeviceToDevice, 0);
    final_kernel<<<RTOT / 4, 512>>>(nf, W_feat, b_feat, out_ending);
}